// round 11
// baseline (speedup 1.0000x reference)
#include <cuda_runtime.h>
#include <cuda_bf16.h>
#include <math.h>

#define N_NODES   100000
#define N_EDGES   1600000
#define FEAT      128
#define N_GRAPHS  512
#define N_CLASSES 10

#define SCAN_ELEMS 512
#define SCAN_NBLK  ((N_NODES + SCAN_ELEMS - 1) / SCAN_ELEMS)   // 196

// ---------------- scratch (device globals; referenced ONLY from device code) --
__device__ int   g_deg[N_NODES];
__device__ int   g_off[N_NODES + 1];
__device__ int   g_cur[N_NODES];
__device__ int   g_csr[N_EDGES];
__device__ float g_cnt[N_NODES];
__device__ int   g_end[N_GRAPHS];
__device__ int   g_bsum[SCAN_NBLK];
__device__ int   g_bpre[SCAN_NBLK];

__device__ __align__(16) __nv_bfloat16 g_hb0[N_NODES * FEAT];   // ping-pong shadows
__device__ __align__(16) __nv_bfloat16 g_hb1[N_NODES * FEAT];
__device__ float g_hA[N_NODES * FEAT];                          // fp32 final output
__device__ float g_gate[N_NODES];

// ---------------- helpers ----------------
__device__ __forceinline__ float tf32r(float x) {
    unsigned r;
    asm("cvt.rna.tf32.f32 %0, %1;" : "=r"(r) : "f"(x));
    return __uint_as_float(r);
}
__device__ __forceinline__ void mma_tf32(float* d, const unsigned* a, const unsigned* b) {
    asm volatile(
        "mma.sync.aligned.m16n8k8.row.col.f32.tf32.tf32.f32 "
        "{%0,%1,%2,%3}, {%4,%5,%6,%7}, {%8,%9}, {%0,%1,%2,%3};"
        : "+f"(d[0]), "+f"(d[1]), "+f"(d[2]), "+f"(d[3])
        : "r"(a[0]), "r"(a[1]), "r"(a[2]), "r"(a[3]), "r"(b[0]), "r"(b[1]));
}
__device__ __forceinline__ void bf4_to_f4(uint2 r, float* o) {
    __nv_bfloat162 p0 = *reinterpret_cast<__nv_bfloat162*>(&r.x);
    __nv_bfloat162 p1 = *reinterpret_cast<__nv_bfloat162*>(&r.y);
    float2 f0 = __bfloat1622float2(p0);
    float2 f1 = __bfloat1622float2(p1);
    o[0] = f0.x; o[1] = f0.y; o[2] = f1.x; o[3] = f1.y;
}

// ---------------- setup: zero deg + boundaries + x -> bf16 shadow0 ------------
__global__ void k_setup(const float* __restrict__ x, const int* __restrict__ batch) {
    int i = blockIdx.x * blockDim.x + threadIdx.x;
    if (i < N_NODES * FEAT / 4) {
        float4 v = __ldg((const float4*)x + i);
        __nv_bfloat162 a = __float22bfloat162_rn(make_float2(v.x, v.y));
        __nv_bfloat162 b = __float22bfloat162_rn(make_float2(v.z, v.w));
        uint2 o;
        o.x = *reinterpret_cast<unsigned*>(&a);
        o.y = *reinterpret_cast<unsigned*>(&b);
        *((uint2*)g_hb0 + i) = o;
    }
    if (i < N_NODES) {
        g_deg[i] = 0;
        int b  = batch[i];
        int bn = (i + 1 < N_NODES) ? batch[i + 1] : N_GRAPHS;
        if (i == 0)
            for (int g = 0; g < b; g++) g_end[g] = 0;
        for (int g = b; g < bn; g++) g_end[g] = i + 1;
    }
}

// ---------------- CSR build (split layout: src=ei[0..E), dst=ei[E..2E)) ------
__global__ void k_hist(const int* __restrict__ ei) {
    int e = blockIdx.x * blockDim.x + threadIdx.x;
    if (e < N_EDGES) atomicAdd(&g_deg[ei[N_EDGES + e]], 1);
}

__global__ void k_scan_a() {
    int b = blockIdx.x, t = threadIdx.x;
    int i0 = b * SCAN_ELEMS + t * 2;
    int d0 = (i0 < N_NODES) ? g_deg[i0] : 0;
    int d1 = (i0 + 1 < N_NODES) ? g_deg[i0 + 1] : 0;
    __shared__ int sh[256];
    sh[t] = d0 + d1;
    __syncthreads();
    for (int s = 128; s > 0; s >>= 1) {
        if (t < s) sh[t] += sh[t + s];
        __syncthreads();
    }
    if (t == 0) g_bsum[b] = sh[0];
}
__global__ void k_scan_b() {
    int t = threadIdx.x;
    __shared__ int sh[256];
    int v = (t < SCAN_NBLK) ? g_bsum[t] : 0;
    sh[t] = v;
    __syncthreads();
    for (int d = 1; d < 256; d <<= 1) {
        int x = (t >= d) ? sh[t - d] : 0;
        __syncthreads();
        sh[t] += x;
        __syncthreads();
    }
    if (t < SCAN_NBLK) g_bpre[t] = sh[t] - v;
}
__global__ void k_scan_c() {
    int b = blockIdx.x, t = threadIdx.x;
    int i0 = b * SCAN_ELEMS + t * 2;
    int d0 = (i0 < N_NODES) ? g_deg[i0] : 0;
    int d1 = (i0 + 1 < N_NODES) ? g_deg[i0 + 1] : 0;
    __shared__ int sh[256];
    int v = d0 + d1;
    sh[t] = v;
    __syncthreads();
    for (int d = 1; d < 256; d <<= 1) {
        int x = (t >= d) ? sh[t - d] : 0;
        __syncthreads();
        sh[t] += x;
        __syncthreads();
    }
    int pre = g_bpre[b] + sh[t] - v;
    if (i0 < N_NODES) {
        g_off[i0] = pre; g_cur[i0] = pre;
        g_cnt[i0] = fmaxf((float)d0, 1.0f);
    }
    if (i0 + 1 < N_NODES) {
        g_off[i0 + 1] = pre + d0; g_cur[i0 + 1] = pre + d0;
        g_cnt[i0 + 1] = fmaxf((float)d1, 1.0f);
    }
    if (b == 0 && t == 0) g_off[N_NODES] = N_EDGES;
}

__global__ void k_scatter(const int* __restrict__ ei) {
    int e = blockIdx.x * blockDim.x + threadIdx.x;
    if (e < N_EDGES) {
        int pos = atomicAdd(&g_cur[ei[N_EDGES + e]], 1);
        g_csr[pos] = ei[e];
    }
}

// ---------------- fused layer: gather-mean (SMEM) + tensor-core GEMM ---------
// result = relu(mean(hin)@W1 + hin@W2 + bias)
// hin/hout ping-pong: in0=1 -> in=g_hb0,out=g_hb1 ; in0=0 -> in=g_hb1,out=g_hb0
// last=1: write fp32 g_hA instead of bf16 shadow.
#define GBM 128
#define GBK 32
#define MPITCH 136                           // bf16 pitch of smem mean tile
#define SM_MEAN_B (GBM * MPITCH * 2)         // 34816
#define SM_AS_B   (GBM * 36 * 4)             // 18432
#define SM_BS_B   (GBK * 136 * 4)            // 17408
#define LAYER_SMEM (SM_MEAN_B + SM_AS_B + SM_BS_B)   // 70656

__global__ __launch_bounds__(256) void k_layer(
    const float* __restrict__ W1, const float* __restrict__ W2,
    const float* __restrict__ bias, int in0, int last, int nrows)
{
    const __nv_bfloat16* __restrict__ hin = in0 ? g_hb0 : g_hb1;
    __nv_bfloat16* __restrict__ hout      = in0 ? g_hb1 : g_hb0;

    extern __shared__ char smraw[];
    __nv_bfloat16* meanS = (__nv_bfloat16*)smraw;                  // [128][136]
    float* As = (float*)(smraw + SM_MEAN_B);                       // [128][36]
    float* Bs = (float*)(smraw + SM_MEAN_B + SM_AS_B);             // [32][136]

    int row0 = blockIdx.x * GBM;
    int tid  = threadIdx.x;
    int lane = tid & 31;
    int wid  = tid >> 5;
    int wm   = wid & 3;
    int wn   = wid >> 2;

    const uint2* __restrict__ inq = (const uint2*)hin;

    // ================= phase 1: gather-mean into meanS =================
    for (int j = 0; j < 16; j++) {
        int row  = wid * 16 + j;
        int grow = row0 + row;
        float ax = 0.f, ay = 0.f, az = 0.f, aw = 0.f, inv = 0.f;
        if (grow < nrows) {
            int s = g_off[grow], e = g_off[grow + 1];
            int i = s;
            for (; i + 8 <= e; i += 8) {
                uint2 r[8];
#pragma unroll
                for (int q = 0; q < 8; q++)
                    r[q] = __ldg(inq + (size_t)__ldg(&g_csr[i + q]) * (FEAT / 4) + lane);
#pragma unroll
                for (int q = 0; q < 8; q++) {
                    float f[4];
                    bf4_to_f4(r[q], f);
                    ax += f[0]; ay += f[1]; az += f[2]; aw += f[3];
                }
            }
            for (; i < e; i++) {
                uint2 r = __ldg(inq + (size_t)__ldg(&g_csr[i]) * (FEAT / 4) + lane);
                float f[4];
                bf4_to_f4(r, f);
                ax += f[0]; ay += f[1]; az += f[2]; aw += f[3];
            }
            inv = 1.0f / g_cnt[grow];
        }
        __nv_bfloat162 a = __float22bfloat162_rn(make_float2(ax * inv, ay * inv));
        __nv_bfloat162 b = __float22bfloat162_rn(make_float2(az * inv, aw * inv));
        uint2 o;
        o.x = *reinterpret_cast<unsigned*>(&a);
        o.y = *reinterpret_cast<unsigned*>(&b);
        *(uint2*)(meanS + row * MPITCH + lane * 4) = o;
    }
    __syncthreads();

    // ================= phase 2: GEMM mainloop =================
    int am = tid >> 3;             // 0..31 (A row base)
    int aq = (tid & 7) * 4;        // A col quad
    int brw = tid >> 5;            // 0..7
    int bc  = (tid & 31) * 4;

    uint2  ar[4];
    float4 brv[4];

    auto load_chunk = [&](int c) {
        int ph = c >> 2, k0 = (c & 3) * GBK;
        const float* __restrict__ W = ph ? W2 : W1;
#pragma unroll
        for (int p = 0; p < 4; p++) {
            brv[p] = *(const float4*)(W + (size_t)(k0 + brw + p * 8) * FEAT + bc);
            if (ph) {
                int grow = row0 + am + p * 32;
                ar[p] = (grow < nrows)
                    ? __ldg(inq + ((size_t)grow * FEAT + k0 + aq) / 4)
                    : make_uint2(0u, 0u);
            }
        }
    };

    float d[2][8][4];
#pragma unroll
    for (int mt = 0; mt < 2; mt++)
#pragma unroll
        for (int nt = 0; nt < 8; nt++)
#pragma unroll
            for (int c = 0; c < 4; c++) d[mt][nt][c] = 0.0f;

    load_chunk(0);
    for (int c = 0; c < 8; c++) {
        int k0 = (c & 3) * GBK;
#pragma unroll
        for (int p = 0; p < 4; p++) {
            int row = am + p * 32;
            float f[4];
            if (c < 4) {
                uint2 r = *(const uint2*)(meanS + row * MPITCH + k0 + aq);
                bf4_to_f4(r, f);
            } else {
                bf4_to_f4(ar[p], f);
            }
            As[row * 36 + aq + 0] = f[0];
            As[row * 36 + aq + 1] = f[1];
            As[row * 36 + aq + 2] = f[2];
            As[row * 36 + aq + 3] = f[3];
            int krow = brw + p * 8;
            Bs[krow * 136 + bc + 0] = tf32r(brv[p].x);
            Bs[krow * 136 + bc + 1] = tf32r(brv[p].y);
            Bs[krow * 136 + bc + 2] = tf32r(brv[p].z);
            Bs[krow * 136 + bc + 3] = tf32r(brv[p].w);
        }
        __syncthreads();
        if (c < 7) load_chunk(c + 1);

#pragma unroll
        for (int ks = 0; ks < 4; ks++) {
            unsigned a[2][4], b[8][2];
            int arow = wm * 32 + (lane >> 2);
            int acol = ks * 8 + (lane & 3);
#pragma unroll
            for (int mt = 0; mt < 2; mt++) {
                int r0 = arow + mt * 16;
                a[mt][0] = __float_as_uint(As[r0 * 36 + acol]);
                a[mt][1] = __float_as_uint(As[(r0 + 8) * 36 + acol]);
                a[mt][2] = __float_as_uint(As[r0 * 36 + acol + 4]);
                a[mt][3] = __float_as_uint(As[(r0 + 8) * 36 + acol + 4]);
            }
            int bk  = ks * 8 + (lane & 3);
            int bn0 = wn * 64 + (lane >> 2);
#pragma unroll
            for (int nt = 0; nt < 8; nt++) {
                b[nt][0] = __float_as_uint(Bs[bk * 136 + bn0 + nt * 8]);
                b[nt][1] = __float_as_uint(Bs[(bk + 4) * 136 + bn0 + nt * 8]);
            }
#pragma unroll
            for (int mt = 0; mt < 2; mt++)
#pragma unroll
                for (int nt = 0; nt < 8; nt++)
                    mma_tf32(d[mt][nt], a[mt], b[nt]);
        }
        __syncthreads();
    }

    // ---- epilogue: bias + relu ----
    int rbase = row0 + wm * 32 + (lane >> 2);
    int cbase = wn * 64 + (lane & 3) * 2;
#pragma unroll
    for (int nt = 0; nt < 8; nt++) {
        int col = cbase + nt * 8;
        float bv0 = __ldg(&bias[col]);
        float bv1 = __ldg(&bias[col + 1]);
#pragma unroll
        for (int mt = 0; mt < 2; mt++) {
#pragma unroll
            for (int half = 0; half < 2; half++) {
                int r = rbase + mt * 16 + half * 8;
                if (r < nrows) {
                    float2 o;
                    o.x = fmaxf(d[mt][nt][half * 2 + 0] + bv0, 0.0f);
                    o.y = fmaxf(d[mt][nt][half * 2 + 1] + bv1, 0.0f);
                    if (last)
                        *(float2*)(g_hA + (size_t)r * FEAT + col) = o;
                    else
                        *(__nv_bfloat162*)(hout + (size_t)r * FEAT + col) =
                            __float22bfloat162_rn(o);
                }
            }
        }
    }
}

// ---------------- fused attention pooling + MLP head (1 block / graph) -------
__global__ __launch_bounds__(128) void k_attnpool(
    const float* __restrict__ gate_w, const float* __restrict__ gate_b,
    const float* __restrict__ lin1_w, const float* __restrict__ lin1_b,
    const float* __restrict__ lin2_w, const float* __restrict__ lin2_b,
    float* __restrict__ out)
{
    int g  = blockIdx.x;
    int lo = (g == 0) ? 0 : g_end[g - 1];
    int hi = g_end[g];
    int t = threadIdx.x, warp = t >> 5, lane = t & 31;

    __shared__ float red4[4];
    __shared__ float s_m, s_s;
    __shared__ float sp[FEAT];
    __shared__ float so[FEAT];
    __shared__ float lg[N_CLASSES];

    float4 wv = *(const float4*)(gate_w + lane * 4);
    float gb = __ldg(&gate_b[0]);
    float lmax = -1e30f;
    for (int node = lo + warp; node < hi; node += 4) {
        float4 hv = *(const float4*)(g_hA + (size_t)node * FEAT + lane * 4);
        float s = hv.x * wv.x + hv.y * wv.y + hv.z * wv.z + hv.w * wv.w;
#pragma unroll
        for (int d = 16; d > 0; d >>= 1) s += __shfl_xor_sync(0xFFFFFFFFu, s, d);
        s += gb;
        if (lane == 0) g_gate[node] = s;
        lmax = fmaxf(lmax, s);
    }
    if (lane == 0) red4[warp] = lmax;
    __syncthreads();
    if (t == 0)
        s_m = fmaxf(fmaxf(red4[0], red4[1]), fmaxf(red4[2], red4[3]));
    __syncthreads();
    float m = s_m;

    float part = 0.0f;
    for (int node = lo + t; node < hi; node += 128) {
        float e = expf(g_gate[node] - m);
        g_gate[node] = e;
        part += e;
    }
#pragma unroll
    for (int d = 16; d > 0; d >>= 1) part += __shfl_xor_sync(0xFFFFFFFFu, part, d);
    if (lane == 0) red4[warp] = part;
    __syncthreads();
    if (t == 0) s_s = red4[0] + red4[1] + red4[2] + red4[3];
    __syncthreads();
    float s = s_s;
    float invs = (s > 0.0f) ? 1.0f / s : 0.0f;

    float acc = 0.0f;
#pragma unroll 4
    for (int node = lo; node < hi; node++)
        acc += g_gate[node] * g_hA[(size_t)node * FEAT + t];
    sp[t] = acc * invs;
    __syncthreads();

    float h1 = lin1_b[t];
#pragma unroll 8
    for (int k = 0; k < FEAT; k++)
        h1 = fmaf(sp[k], lin1_w[(size_t)k * FEAT + t], h1);
    so[t] = fmaxf(h1, 0.0f);
    __syncthreads();

    if (t < N_CLASSES) {
        float a = lin2_b[t];
#pragma unroll 8
        for (int k = 0; k < FEAT; k++)
            a = fmaf(so[k], lin2_w[(size_t)k * N_CLASSES + t], a);
        lg[t] = a;
    }
    __syncthreads();

    if (t == 0) {
        float mx = lg[0];
#pragma unroll
        for (int j = 1; j < N_CLASSES; j++) mx = fmaxf(mx, lg[j]);
        float se = 0.0f;
#pragma unroll
        for (int j = 0; j < N_CLASSES; j++) se += expf(lg[j] - mx);
        float l = logf(se);
#pragma unroll
        for (int j = 0; j < N_CLASSES; j++)
            out[(size_t)g * N_CLASSES + j] = lg[j] - mx - l;
    }
}

// ---------------- launch ----------------
extern "C" void kernel_launch(void* const* d_in, const int* in_sizes, int n_in,
                              void* d_out, int out_size) {
    const float* x      = (const float*)d_in[0];
    const int*   ei     = (const int*)  d_in[1];
    const int*   batch  = (const int*)  d_in[2];
    const float* w1l = (const float*)d_in[3];
    const float* b1  = (const float*)d_in[4];
    const float* w1r = (const float*)d_in[5];
    const float* w2l = (const float*)d_in[6];
    const float* b2  = (const float*)d_in[7];
    const float* w2r = (const float*)d_in[8];
    const float* w3l = (const float*)d_in[9];
    const float* b3  = (const float*)d_in[10];
    const float* w3r = (const float*)d_in[11];
    const float* gate_w = (const float*)d_in[12];
    const float* gate_b = (const float*)d_in[13];
    const float* lin1_w = (const float*)d_in[14];
    const float* lin1_b = (const float*)d_in[15];
    const float* lin2_w = (const float*)d_in[16];
    const float* lin2_b = (const float*)d_in[17];
    float* out = (float*)d_out;

    const int TB = 256;

    cudaFuncSetAttribute(k_layer, cudaFuncAttributeMaxDynamicSharedMemorySize,
                         LAYER_SMEM);

    k_setup<<<(N_NODES * FEAT / 4 + TB - 1) / TB, TB>>>(x, batch);
    k_hist<<<(N_EDGES + TB - 1) / TB, TB>>>(ei);
    k_scan_a<<<SCAN_NBLK, 256>>>();
    k_scan_b<<<1, 256>>>();
    k_scan_c<<<SCAN_NBLK, 256>>>();
    k_scatter<<<(N_EDGES + TB - 1) / TB, TB>>>(ei);

    int layer_blocks = (N_NODES + GBM - 1) / GBM;

    // layer 1: hb1 <- relu(mean(hb0)@w1l + hb0@w1r + b1)
    k_layer<<<layer_blocks, 256, LAYER_SMEM>>>(w1l, w1r, b1, 1, 0, N_NODES);
    // layer 2: hb0 <- relu(mean(hb1)@w2l + hb1@w2r + b2)
    k_layer<<<layer_blocks, 256, LAYER_SMEM>>>(w2l, w2r, b2, 0, 0, N_NODES);
    // layer 3: g_hA (fp32) <- relu(mean(hb0)@w3l + hb0@w3r + b3)
    k_layer<<<layer_blocks, 256, LAYER_SMEM>>>(w3l, w3r, b3, 1, 1, N_NODES);

    // fused attentional aggregation + head
    k_attnpool<<<N_GRAPHS, 128>>>(gate_w, gate_b, lin1_w, lin1_b,
                                  lin2_w, lin2_b, out);
}

// round 12
// speedup vs baseline: 1.2535x; 1.2535x over previous
#include <cuda_runtime.h>
#include <cuda_bf16.h>
#include <cuda_fp16.h>
#include <math.h>

#define N_NODES   100000
#define N_EDGES   1600000
#define FEAT      128
#define N_GRAPHS  512
#define N_CLASSES 10

#define SCAN_ELEMS 512
#define SCAN_NBLK  ((N_NODES + SCAN_ELEMS - 1) / SCAN_ELEMS)   // 196

// ---------------- scratch (device globals; referenced ONLY from device code) --
__device__ int   g_deg[N_NODES];
__device__ int   g_off[N_NODES + 1];
__device__ int   g_cur[N_NODES];
__device__ int   g_csr[N_EDGES];
__device__ float g_cnt[N_NODES];
__device__ int   g_end[N_GRAPHS];
__device__ int   g_bsum[SCAN_NBLK];
__device__ int   g_bpre[SCAN_NBLK];

__device__ __align__(16) __nv_bfloat16 g_hb[N_NODES * FEAT];    // bf16 shadow (in-place across layers)
__device__ __align__(16) __nv_bfloat16 g_meanb[N_NODES * FEAT]; // bf16 neighbor-mean
__device__ __align__(16) unsigned g_f8[N_NODES * FEAT / 4];     // fp8 e4m3 gather shadow
__device__ float g_hA[N_NODES * FEAT];                          // fp32 final-layer output
__device__ float g_gate[N_NODES];

// ---------------- helpers ----------------
__device__ __forceinline__ float tf32r(float x) {
    unsigned r;
    asm("cvt.rna.tf32.f32 %0, %1;" : "=r"(r) : "f"(x));
    return __uint_as_float(r);
}
__device__ __forceinline__ void mma_tf32(float* d, const unsigned* a, const unsigned* b) {
    asm volatile(
        "mma.sync.aligned.m16n8k8.row.col.f32.tf32.tf32.f32 "
        "{%0,%1,%2,%3}, {%4,%5,%6,%7}, {%8,%9}, {%0,%1,%2,%3};"
        : "+f"(d[0]), "+f"(d[1]), "+f"(d[2]), "+f"(d[3])
        : "r"(a[0]), "r"(a[1]), "r"(a[2]), "r"(a[3]), "r"(b[0]), "r"(b[1]));
}
__device__ __forceinline__ void bf4_to_f4(uint2 r, float* o) {
    __nv_bfloat162 p0 = *reinterpret_cast<__nv_bfloat162*>(&r.x);
    __nv_bfloat162 p1 = *reinterpret_cast<__nv_bfloat162*>(&r.y);
    float2 f0 = __bfloat1622float2(p0);
    float2 f1 = __bfloat1622float2(p1);
    o[0] = f0.x; o[1] = f0.y; o[2] = f1.x; o[3] = f1.y;
}
__device__ __forceinline__ unsigned short f2_to_fp8x2(float lo, float hi) {
    unsigned short r;
    asm("cvt.rn.satfinite.e4m3x2.f32 %0, %1, %2;" : "=h"(r) : "f"(hi), "f"(lo));
    return r;    // byte0 = lo, byte1 = hi
}
__device__ __forceinline__ unsigned f4_to_fp8x4(float a, float b, float c, float d) {
    unsigned short lo = f2_to_fp8x2(a, b);
    unsigned short hi = f2_to_fp8x2(c, d);
    return (unsigned)lo | ((unsigned)hi << 16);
}
__device__ __forceinline__ void fp8x4_to_f4(unsigned r, float* o) {
    unsigned short lo = (unsigned short)(r & 0xFFFFu);
    unsigned short hi = (unsigned short)(r >> 16);
    unsigned h01, h23;
    asm("cvt.rn.f16x2.e4m3x2 %0, %1;" : "=r"(h01) : "h"(lo));   // exact
    asm("cvt.rn.f16x2.e4m3x2 %0, %1;" : "=r"(h23) : "h"(hi));
    __half2 p0 = *reinterpret_cast<__half2*>(&h01);
    __half2 p1 = *reinterpret_cast<__half2*>(&h23);
    float2 f0 = __half22float2(p0);
    float2 f1 = __half22float2(p1);
    o[0] = f0.x; o[1] = f0.y; o[2] = f1.x; o[3] = f1.y;
}

// ---------------- setup: zero deg + boundaries + x -> bf16/fp8 shadows --------
__global__ void k_setup(const float* __restrict__ x, const int* __restrict__ batch) {
    int i = blockIdx.x * blockDim.x + threadIdx.x;
    if (i < N_NODES * FEAT / 4) {
        float4 v = __ldg((const float4*)x + i);
        __nv_bfloat162 a = __float22bfloat162_rn(make_float2(v.x, v.y));
        __nv_bfloat162 b = __float22bfloat162_rn(make_float2(v.z, v.w));
        uint2 o;
        o.x = *reinterpret_cast<unsigned*>(&a);
        o.y = *reinterpret_cast<unsigned*>(&b);
        *((uint2*)g_hb + i) = o;
        g_f8[i] = f4_to_fp8x4(v.x, v.y, v.z, v.w);
    }
    if (i < N_NODES) {
        g_deg[i] = 0;
        int b  = batch[i];
        int bn = (i + 1 < N_NODES) ? batch[i + 1] : N_GRAPHS;
        if (i == 0)
            for (int g = 0; g < b; g++) g_end[g] = 0;
        for (int g = b; g < bn; g++) g_end[g] = i + 1;
    }
}

// ---------------- CSR build (split layout: src=ei[0..E), dst=ei[E..2E)) ------
__global__ void k_hist(const int* __restrict__ ei) {
    int e = blockIdx.x * blockDim.x + threadIdx.x;
    if (e < N_EDGES) atomicAdd(&g_deg[ei[N_EDGES + e]], 1);
}

__global__ void k_scan_a() {
    int b = blockIdx.x, t = threadIdx.x;
    int i0 = b * SCAN_ELEMS + t * 2;
    int d0 = (i0 < N_NODES) ? g_deg[i0] : 0;
    int d1 = (i0 + 1 < N_NODES) ? g_deg[i0 + 1] : 0;
    __shared__ int sh[256];
    sh[t] = d0 + d1;
    __syncthreads();
    for (int s = 128; s > 0; s >>= 1) {
        if (t < s) sh[t] += sh[t + s];
        __syncthreads();
    }
    if (t == 0) g_bsum[b] = sh[0];
}
__global__ void k_scan_b() {
    int t = threadIdx.x;
    __shared__ int sh[256];
    int v = (t < SCAN_NBLK) ? g_bsum[t] : 0;
    sh[t] = v;
    __syncthreads();
    for (int d = 1; d < 256; d <<= 1) {
        int x = (t >= d) ? sh[t - d] : 0;
        __syncthreads();
        sh[t] += x;
        __syncthreads();
    }
    if (t < SCAN_NBLK) g_bpre[t] = sh[t] - v;
}
__global__ void k_scan_c() {
    int b = blockIdx.x, t = threadIdx.x;
    int i0 = b * SCAN_ELEMS + t * 2;
    int d0 = (i0 < N_NODES) ? g_deg[i0] : 0;
    int d1 = (i0 + 1 < N_NODES) ? g_deg[i0 + 1] : 0;
    __shared__ int sh[256];
    int v = d0 + d1;
    sh[t] = v;
    __syncthreads();
    for (int d = 1; d < 256; d <<= 1) {
        int x = (t >= d) ? sh[t - d] : 0;
        __syncthreads();
        sh[t] += x;
        __syncthreads();
    }
    int pre = g_bpre[b] + sh[t] - v;
    if (i0 < N_NODES) {
        g_off[i0] = pre; g_cur[i0] = pre;
        g_cnt[i0] = fmaxf((float)d0, 1.0f);
    }
    if (i0 + 1 < N_NODES) {
        g_off[i0 + 1] = pre + d0; g_cur[i0 + 1] = pre + d0;
        g_cnt[i0 + 1] = fmaxf((float)d1, 1.0f);
    }
    if (b == 0 && t == 0) g_off[N_NODES] = N_EDGES;
}

__global__ void k_scatter(const int* __restrict__ ei) {
    int e = blockIdx.x * blockDim.x + threadIdx.x;
    if (e < N_EDGES) {
        int pos = atomicAdd(&g_cur[ei[N_EDGES + e]], 1);
        g_csr[pos] = ei[e];
    }
}

// ---------------- mean aggregation: warp/node, fp8 gather, bf16 out ----------
__global__ __launch_bounds__(256) void k_agg() {
    int node = (blockIdx.x * blockDim.x + threadIdx.x) >> 5;
    int lane = threadIdx.x & 31;
    if (node >= N_NODES) return;
    int s = g_off[node], e = g_off[node + 1];
    float ax = 0.f, ay = 0.f, az = 0.f, aw = 0.f;
    int i = s;
    for (; i + 4 <= e; i += 4) {
        int n0 = g_csr[i], n1 = g_csr[i + 1], n2 = g_csr[i + 2], n3 = g_csr[i + 3];
        unsigned r0 = __ldg(g_f8 + (size_t)n0 * (FEAT / 4) + lane);
        unsigned r1 = __ldg(g_f8 + (size_t)n1 * (FEAT / 4) + lane);
        unsigned r2 = __ldg(g_f8 + (size_t)n2 * (FEAT / 4) + lane);
        unsigned r3 = __ldg(g_f8 + (size_t)n3 * (FEAT / 4) + lane);
        float f[4];
        fp8x4_to_f4(r0, f); ax += f[0]; ay += f[1]; az += f[2]; aw += f[3];
        fp8x4_to_f4(r1, f); ax += f[0]; ay += f[1]; az += f[2]; aw += f[3];
        fp8x4_to_f4(r2, f); ax += f[0]; ay += f[1]; az += f[2]; aw += f[3];
        fp8x4_to_f4(r3, f); ax += f[0]; ay += f[1]; az += f[2]; aw += f[3];
    }
    for (; i < e; i++) {
        unsigned r0 = __ldg(g_f8 + (size_t)g_csr[i] * (FEAT / 4) + lane);
        float f[4];
        fp8x4_to_f4(r0, f); ax += f[0]; ay += f[1]; az += f[2]; aw += f[3];
    }
    float inv = 1.0f / g_cnt[node];
    __nv_bfloat162 a = __float22bfloat162_rn(make_float2(ax * inv, ay * inv));
    __nv_bfloat162 b = __float22bfloat162_rn(make_float2(az * inv, aw * inv));
    uint2 o;
    o.x = *reinterpret_cast<unsigned*>(&a);
    o.y = *reinterpret_cast<unsigned*>(&b);
    *((uint2*)g_meanb + (size_t)node * (FEAT / 4) + lane) = o;
}

// ---------------- tensor-core fused GEMM, bf16 A operands, tf32 weights ------
// result = relu(mean@W1 + h@W2 + bias)
// last=0: write bf16 shadow in place + fp8 shadow; last=1: write fp32 g_hA
#define GBM 128
#define GBK 32
__global__ __launch_bounds__(256) void k_gemm_tc(
    const float* __restrict__ W1, const float* __restrict__ W2,
    const float* __restrict__ bias, int last, int nrows)
{
    __shared__ float As[GBM][36];
    __shared__ float Bs[GBK][136];

    int row0 = blockIdx.x * GBM;
    int tid  = threadIdx.x;
    int lane = tid & 31;
    int wid  = tid >> 5;
    int wm   = wid & 3;
    int wn   = wid >> 2;

    int am = tid >> 3;             // 0..31 (A row base)
    int aq = (tid & 7) * 4;        // A col quad
    int brw = tid >> 5;            // 0..7
    int bc  = (tid & 31) * 4;

    uint2  ar[4];
    float4 brv[4];

    auto load_chunk = [&](int c) {
        int ph = c >> 2, k0 = (c & 3) * GBK;
        const uint2* __restrict__ Ab = ph ? (const uint2*)g_hb : (const uint2*)g_meanb;
        const float* __restrict__ W  = ph ? W2 : W1;
#pragma unroll
        for (int p = 0; p < 4; p++) {
            int grow = row0 + am + p * 32;
            ar[p] = (grow < nrows)
                ? __ldg(Ab + ((size_t)grow * FEAT + k0 + aq) / 4)
                : make_uint2(0u, 0u);
            brv[p] = *(const float4*)(W + (size_t)(k0 + brw + p * 8) * FEAT + bc);
        }
    };

    float d[2][8][4];
#pragma unroll
    for (int mt = 0; mt < 2; mt++)
#pragma unroll
        for (int nt = 0; nt < 8; nt++)
#pragma unroll
            for (int c = 0; c < 4; c++) d[mt][nt][c] = 0.0f;

    load_chunk(0);
    for (int c = 0; c < 8; c++) {
#pragma unroll
        for (int p = 0; p < 4; p++) {
            int row = am + p * 32;
            float f[4];
            bf4_to_f4(ar[p], f);           // bf16 subset of tf32: no cvt needed
            As[row][aq + 0] = f[0];
            As[row][aq + 1] = f[1];
            As[row][aq + 2] = f[2];
            As[row][aq + 3] = f[3];
            int krow = brw + p * 8;
            Bs[krow][bc + 0] = tf32r(brv[p].x);
            Bs[krow][bc + 1] = tf32r(brv[p].y);
            Bs[krow][bc + 2] = tf32r(brv[p].z);
            Bs[krow][bc + 3] = tf32r(brv[p].w);
        }
        __syncthreads();
        if (c < 7) load_chunk(c + 1);

#pragma unroll
        for (int ks = 0; ks < 4; ks++) {
            unsigned a[2][4], b[8][2];
            int arow = wm * 32 + (lane >> 2);
            int acol = ks * 8 + (lane & 3);
#pragma unroll
            for (int mt = 0; mt < 2; mt++) {
                int r0 = arow + mt * 16;
                a[mt][0] = __float_as_uint(As[r0][acol]);
                a[mt][1] = __float_as_uint(As[r0 + 8][acol]);
                a[mt][2] = __float_as_uint(As[r0][acol + 4]);
                a[mt][3] = __float_as_uint(As[r0 + 8][acol + 4]);
            }
            int bk  = ks * 8 + (lane & 3);
            int bn0 = wn * 64 + (lane >> 2);
#pragma unroll
            for (int nt = 0; nt < 8; nt++) {
                b[nt][0] = __float_as_uint(Bs[bk][bn0 + nt * 8]);
                b[nt][1] = __float_as_uint(Bs[bk + 4][bn0 + nt * 8]);
            }
#pragma unroll
            for (int mt = 0; mt < 2; mt++)
#pragma unroll
                for (int nt = 0; nt < 8; nt++)
                    mma_tf32(d[mt][nt], a[mt], b[nt]);
        }
        __syncthreads();
    }

    // ---- epilogue: bias + relu ----
    int rbase = row0 + wm * 32 + (lane >> 2);
    int cbase = wn * 64 + (lane & 3) * 2;
    unsigned short* f8s = (unsigned short*)g_f8;
#pragma unroll
    for (int nt = 0; nt < 8; nt++) {
        int col = cbase + nt * 8;
        float bv0 = __ldg(&bias[col]);
        float bv1 = __ldg(&bias[col + 1]);
#pragma unroll
        for (int mt = 0; mt < 2; mt++) {
#pragma unroll
            for (int half = 0; half < 2; half++) {
                int r = rbase + mt * 16 + half * 8;
                if (r < nrows) {
                    float2 o;
                    o.x = fmaxf(d[mt][nt][half * 2 + 0] + bv0, 0.0f);
                    o.y = fmaxf(d[mt][nt][half * 2 + 1] + bv1, 0.0f);
                    if (last) {
                        *(float2*)(g_hA + (size_t)r * FEAT + col) = o;
                    } else {
                        *(__nv_bfloat162*)(g_hb + (size_t)r * FEAT + col) =
                            __float22bfloat162_rn(o);
                        f8s[((size_t)r * FEAT + col) >> 1] = f2_to_fp8x2(o.x, o.y);
                    }
                }
            }
        }
    }
}

// ---------------- fused attention pooling + MLP head (1 block / graph) -------
__global__ __launch_bounds__(128) void k_attnpool(
    const float* __restrict__ gate_w, const float* __restrict__ gate_b,
    const float* __restrict__ lin1_w, const float* __restrict__ lin1_b,
    const float* __restrict__ lin2_w, const float* __restrict__ lin2_b,
    float* __restrict__ out)
{
    int g  = blockIdx.x;
    int lo = (g == 0) ? 0 : g_end[g - 1];
    int hi = g_end[g];
    int t = threadIdx.x, warp = t >> 5, lane = t & 31;

    __shared__ float red4[4];
    __shared__ float s_m, s_s;
    __shared__ float sp[FEAT];
    __shared__ float so[FEAT];
    __shared__ float lg[N_CLASSES];

    float4 wv = *(const float4*)(gate_w + lane * 4);
    float gb = __ldg(&gate_b[0]);
    float lmax = -1e30f;
    for (int node = lo + warp; node < hi; node += 4) {
        float4 hv = *(const float4*)(g_hA + (size_t)node * FEAT + lane * 4);
        float s = hv.x * wv.x + hv.y * wv.y + hv.z * wv.z + hv.w * wv.w;
#pragma unroll
        for (int d = 16; d > 0; d >>= 1) s += __shfl_xor_sync(0xFFFFFFFFu, s, d);
        s += gb;
        if (lane == 0) g_gate[node] = s;
        lmax = fmaxf(lmax, s);
    }
    if (lane == 0) red4[warp] = lmax;
    __syncthreads();
    if (t == 0)
        s_m = fmaxf(fmaxf(red4[0], red4[1]), fmaxf(red4[2], red4[3]));
    __syncthreads();
    float m = s_m;

    float part = 0.0f;
    for (int node = lo + t; node < hi; node += 128) {
        float e = expf(g_gate[node] - m);
        g_gate[node] = e;
        part += e;
    }
#pragma unroll
    for (int d = 16; d > 0; d >>= 1) part += __shfl_xor_sync(0xFFFFFFFFu, part, d);
    if (lane == 0) red4[warp] = part;
    __syncthreads();
    if (t == 0) s_s = red4[0] + red4[1] + red4[2] + red4[3];
    __syncthreads();
    float s = s_s;
    float invs = (s > 0.0f) ? 1.0f / s : 0.0f;

    float acc = 0.0f;
#pragma unroll 4
    for (int node = lo; node < hi; node++)
        acc += g_gate[node] * g_hA[(size_t)node * FEAT + t];
    sp[t] = acc * invs;
    __syncthreads();

    float h1 = lin1_b[t];
#pragma unroll 8
    for (int k = 0; k < FEAT; k++)
        h1 = fmaf(sp[k], lin1_w[(size_t)k * FEAT + t], h1);
    so[t] = fmaxf(h1, 0.0f);
    __syncthreads();

    if (t < N_CLASSES) {
        float a = lin2_b[t];
#pragma unroll 8
        for (int k = 0; k < FEAT; k++)
            a = fmaf(so[k], lin2_w[(size_t)k * N_CLASSES + t], a);
        lg[t] = a;
    }
    __syncthreads();

    if (t == 0) {
        float mx = lg[0];
#pragma unroll
        for (int j = 1; j < N_CLASSES; j++) mx = fmaxf(mx, lg[j]);
        float se = 0.0f;
#pragma unroll
        for (int j = 0; j < N_CLASSES; j++) se += expf(lg[j] - mx);
        float l = logf(se);
#pragma unroll
        for (int j = 0; j < N_CLASSES; j++)
            out[(size_t)g * N_CLASSES + j] = lg[j] - mx - l;
    }
}

// ---------------- launch ----------------
extern "C" void kernel_launch(void* const* d_in, const int* in_sizes, int n_in,
                              void* d_out, int out_size) {
    const float* x      = (const float*)d_in[0];
    const int*   ei     = (const int*)  d_in[1];
    const int*   batch  = (const int*)  d_in[2];
    const float* w1l = (const float*)d_in[3];
    const float* b1  = (const float*)d_in[4];
    const float* w1r = (const float*)d_in[5];
    const float* w2l = (const float*)d_in[6];
    const float* b2  = (const float*)d_in[7];
    const float* w2r = (const float*)d_in[8];
    const float* w3l = (const float*)d_in[9];
    const float* b3  = (const float*)d_in[10];
    const float* w3r = (const float*)d_in[11];
    const float* gate_w = (const float*)d_in[12];
    const float* gate_b = (const float*)d_in[13];
    const float* lin1_w = (const float*)d_in[14];
    const float* lin1_b = (const float*)d_in[15];
    const float* lin2_w = (const float*)d_in[16];
    const float* lin2_b = (const float*)d_in[17];
    float* out = (float*)d_out;

    const int TB = 256;

    k_setup<<<(N_NODES * FEAT / 4 + TB - 1) / TB, TB>>>(x, batch);
    k_hist<<<(N_EDGES + TB - 1) / TB, TB>>>(ei);
    k_scan_a<<<SCAN_NBLK, 256>>>();
    k_scan_b<<<1, 256>>>();
    k_scan_c<<<SCAN_NBLK, 256>>>();
    k_scatter<<<(N_EDGES + TB - 1) / TB, TB>>>(ei);

    int agg_blocks  = (N_NODES * 32 + TB - 1) / TB;
    int gemm_blocks = (N_NODES + GBM - 1) / GBM;

    // layer 1: shadow <- relu(mean(shadow)@w1l + shadow@w1r + b1)
    k_agg<<<agg_blocks, TB>>>();
    k_gemm_tc<<<gemm_blocks, 256>>>(w1l, w1r, b1, 0, N_NODES);
    // layer 2
    k_agg<<<agg_blocks, TB>>>();
    k_gemm_tc<<<gemm_blocks, 256>>>(w2l, w2r, b2, 0, N_NODES);
    // layer 3: fp32 out for pooling
    k_agg<<<agg_blocks, TB>>>();
    k_gemm_tc<<<gemm_blocks, 256>>>(w3l, w3r, b3, 1, N_NODES);

    // fused attentional aggregation + head
    k_attnpool<<<N_GRAPHS, 128>>>(gate_w, gate_b, lin1_w, lin1_b,
                                  lin2_w, lin2_b, out);
}